// round 2
// baseline (speedup 1.0000x reference)
#include <cuda_runtime.h>
#include <cstdint>

// Problem constants
#define NB 32
#define H 640
#define W 640
#define HW (H*W)            // 409600
#define BOT 448             // int(640*0.7)
#define RH 192              // region rows
#define TW 64               // strip width
#define HALO 5
#define TWH (TW + 2*HALO)   // 74
#define NSTRIP (W/TW)       // 10
#define STRIP_BLOCKS (NB*NSTRIP)   // 320
#define PLAIN_BLOCKS 568
#define TOTAL_BLOCKS (STRIP_BLOCKS + PLAIN_BLOCKS)  // 888
#define THREADS 256
#define TOP_F4_PER_IMG ((BOT*W)/4) // 71680
#define TOP_F4_TOTAL (NB*TOP_F4_PER_IMG)
#define IMG_F4_STRIDE (HW/4)       // 102400

// Per-block partial sums: [block][0]=sum_mask, [1]=sum_bce*mask,
// [2]=sum_combined, [3]=sum_bce*combined. Written unconditionally by every
// block every launch -> deterministic under graph replay, no pre-zeroing.
__device__ double g_part[TOTAL_BLOCKS][4];

__device__ __forceinline__ uint32_t bits_below(int k) {
    if (k <= 0) return 0u;
    if (k >= 32) return 0xFFFFFFFFu;
    return (1u << k) - 1u;
}

__device__ __forceinline__ float bce_f(float l, float t) {
    return fmaxf(l, 0.f) - l * t + log1pf(expf(-fabsf(l)));
}

__device__ __forceinline__ void hsh(uint32_t w0, uint32_t w1, uint32_t w2,
                                    uint32_t& h0, uint32_t& h1, uint32_t& h2) {
    h0 = w0 | (w0 << 1) | (w0 >> 1) | (w1 << 31);
    h1 = w1 | (w1 << 1) | (w0 >> 31) | (w1 >> 1) | (w2 << 31);
    h2 = w2 | (w2 << 1) | (w1 >> 31) | (w2 >> 1);
}

// One 3x3 morphology pass over bit-packed rows. erode == ~dilate(~m & valid) & valid,
// which reproduces lax.reduce_window SAME semantics (OOB = identity element).
__device__ __forceinline__ void morph_pass(uint32_t (*in)[4], uint32_t (*out)[4],
                                           bool erode, const uint32_t* vm, int tid) {
    if (tid < RH) {
        int r = tid;
        uint32_t a0 = 0, a1 = 0, a2 = 0;
        #pragma unroll
        for (int dr = -1; dr <= 1; dr++) {
            int rr = r + dr;
            if ((unsigned)rr < (unsigned)RH) {
                uint32_t w0 = in[rr][0], w1 = in[rr][1], w2 = in[rr][2];
                if (erode) { w0 = ~w0 & vm[0]; w1 = ~w1 & vm[1]; w2 = ~w2 & vm[2]; }
                uint32_t h0, h1, h2;
                hsh(w0, w1, w2, h0, h1, h2);
                a0 |= h0; a1 |= h1; a2 |= h2;
            }
        }
        if (erode) { a0 = ~a0; a1 = ~a1; a2 = ~a2; }
        out[r][0] = a0 & vm[0];
        out[r][1] = a1 & vm[1];
        out[r][2] = a2 & vm[2];
        out[r][3] = 0u;
    }
    __syncthreads();
}

__global__ __launch_bounds__(THREADS)
void loss_kernel(const float* __restrict__ pred, const float* __restrict__ gt,
                 const float* __restrict__ mask, const float* __restrict__ img)
{
    __shared__ uint8_t  s_gray[RH][80];     // gray tile, stride 80
    __shared__ uint32_t s_bA[RH][4];
    __shared__ uint32_t s_bB[RH][4];
    __shared__ float    s_red[8][4];

    const int tid = threadIdx.x;
    const int bx  = blockIdx.x;

    float sm = 0.f, sbm = 0.f, sc = 0.f, sbc = 0.f;

    if (bx < STRIP_BLOCKS) {
        // ---------------- subtitle-region strip block ----------------
        const int n = bx / NSTRIP;
        const int strip = bx - n * NSTRIP;
        const int c0 = strip * TW - HALO;             // may be negative
        const float* ib = img + (size_t)n * 3 * HW;

        // Load gray tile (u8). gray = rint(0.114*b + 0.587*g + 0.299*r) of floor-clipped u8.
        for (int idx = tid; idx < RH * TWH; idx += THREADS) {
            int r = idx / TWH;
            int t = idx - r * TWH;
            int gc = c0 + t;
            int g8 = 0;
            if ((unsigned)gc < (unsigned)W) {
                int base = (BOT + r) * W + gc;
                float b  = ib[base];
                float g  = ib[base + HW];
                float rr = ib[base + 2 * HW];
                b  = fminf(fmaxf(floorf(__fmul_rn(b , 255.f)), 0.f), 255.f);
                g  = fminf(fmaxf(floorf(__fmul_rn(g , 255.f)), 0.f), 255.f);
                rr = fminf(fmaxf(floorf(__fmul_rn(rr, 255.f)), 0.f), 255.f);
                float gf = __fadd_rn(__fadd_rn(__fmul_rn(0.114f, b),
                                               __fmul_rn(0.587f, g)),
                                     __fmul_rn(0.299f, rr));
                g8 = (int)rintf(gf);   // round-half-even, matches jnp.round
            }
            s_gray[r][t] = (uint8_t)g8;
        }
        __syncthreads();

        // Valid-column bitmask (tile cols mapping into [0, W))
        const int lo = (c0 < 0) ? -c0 : 0;
        const int hi = min(TWH, W - c0);
        uint32_t vm[4];
        #pragma unroll
        for (int j = 0; j < 4; j++)
            vm[j] = bits_below(hi - j * 32) & ~bits_below(lo - j * 32);

        // m0 = bright & contrast (bit-packed per row). Laplacian with reflect padding
        // at *region* borders; tile-edge cols (t==0 / t==TWH-1 away from image border)
        // lie in the 1-col shrink zone: their m0 only influences final-mask cols
        // within distance 4, i.e. halo cols never consumed.
        if (tid < RH) {
            int r = tid;
            uint32_t wq0 = 0, wq1 = 0, wq2 = 0;
            for (int t = 0; t < TWH; t++) {
                int gc = c0 + t;
                if ((unsigned)gc >= (unsigned)W) continue;
                int c = s_gray[r][t];
                if (c < 205) continue;   // bright: integer gray > 204.0000000116
                int up = (r == 0)      ? s_gray[1][t]      : s_gray[r - 1][t];
                int dn = (r == RH - 1) ? s_gray[RH - 2][t] : s_gray[r + 1][t];
                int lf, rt_;
                if (gc == 0)            lf = s_gray[r][t + 1];      // reflect
                else if (t == 0)        continue;                   // shrink zone
                else                    lf = s_gray[r][t - 1];
                if (gc == W - 1)        rt_ = s_gray[r][t - 1];     // reflect
                else if (t == TWH - 1)  continue;                   // shrink zone
                else                    rt_ = s_gray[r][t + 1];
                int lap = up + dn + lf + rt_ - 4 * c;
                if (lap >= 77 || lap <= -77) {                      // |lap| > 76.4999...
                    if (t < 32)       wq0 |= (1u << t);
                    else if (t < 64)  wq1 |= (1u << (t - 32));
                    else              wq2 |= (1u << (t - 64));
                }
            }
            s_bA[r][0] = wq0 & vm[0];
            s_bA[r][1] = wq1 & vm[1];
            s_bA[r][2] = wq2 & vm[2];
            s_bA[r][3] = 0u;
        }
        __syncthreads();

        // close (dilate, erode) then open (erode, dilate)
        morph_pass(s_bA, s_bB, false, vm, tid);  // m1 = dilate(m0)
        morph_pass(s_bB, s_bA, true,  vm, tid);  // m2 = erode(m1)
        morph_pass(s_bA, s_bB, true,  vm, tid);  // m3 = erode(m2)
        morph_pass(s_bB, s_bA, false, vm, tid);  // m4 = dilate(m3)  -> final in s_bA

        // Accumulate region sums (base + combined) over the 64-wide center.
        const int cbase = c0 + HALO;  // = strip*64, float4-aligned
        for (int idx = tid; idx < RH * (TW / 4); idx += THREADS) {  // 3072 iters
            int r = idx >> 4;
            int q = idx & 15;
            size_t e = (size_t)n * HW + (size_t)(BOT + r) * W + cbase + q * 4;
            float4 mk = *(const float4*)(mask + e);
            float4 l  = *(const float4*)(pred + e);
            float4 tg = *(const float4*)(gt   + e);
            float b0 = bce_f(l.x, tg.x);
            float b1 = bce_f(l.y, tg.y);
            float b2 = bce_f(l.z, tg.z);
            float b3 = bce_f(l.w, tg.w);
            sm  += mk.x + mk.y + mk.z + mk.w;
            sbm += b0 * mk.x + b1 * mk.y + b2 * mk.z + b3 * mk.w;

            uint32_t w0 = s_bA[r][0], w1 = s_bA[r][1], w2 = s_bA[r][2];
            int t = HALO + q * 4;
            #pragma unroll
            for (int i = 0; i < 4; i++) {
                int tt = t + i;
                uint32_t bit = (tt < 32) ? (w0 >> tt)
                             : (tt < 64) ? (w1 >> (tt - 32))
                                         : (w2 >> (tt - 64));
                float f = (float)(bit & 1u);
                float mki = (i == 0) ? mk.x : (i == 1) ? mk.y : (i == 2) ? mk.z : mk.w;
                float bi  = (i == 0) ? b0   : (i == 1) ? b1   : (i == 2) ? b2   : b3;
                sc  += f * mki;
                sbc += f * bi * mki;
            }
        }
    } else {
        // ---------------- plain block: rows [0, 448) ----------------
        const int lid = bx - STRIP_BLOCKS;
        const float4* p4 = (const float4*)pred;
        const float4* g4 = (const float4*)gt;
        const float4* m4 = (const float4*)mask;
        for (int i = lid * THREADS + tid; i < TOP_F4_TOTAL; i += PLAIN_BLOCKS * THREADS) {
            int n   = i / TOP_F4_PER_IMG;
            int off = i - n * TOP_F4_PER_IMG;
            int e   = n * IMG_F4_STRIDE + off;
            float4 mk = m4[e];
            float4 l  = p4[e];
            float4 tg = g4[e];
            sm  += mk.x + mk.y + mk.z + mk.w;
            sbm += bce_f(l.x, tg.x) * mk.x + bce_f(l.y, tg.y) * mk.y
                 + bce_f(l.z, tg.z) * mk.z + bce_f(l.w, tg.w) * mk.w;
        }
    }

    // ---------------- in-block reduction -> per-block slot ----------------
    #pragma unroll
    for (int o = 16; o; o >>= 1) {
        sm  += __shfl_down_sync(0xFFFFFFFFu, sm,  o);
        sbm += __shfl_down_sync(0xFFFFFFFFu, sbm, o);
        sc  += __shfl_down_sync(0xFFFFFFFFu, sc,  o);
        sbc += __shfl_down_sync(0xFFFFFFFFu, sbc, o);
    }
    int warp = tid >> 5, lane = tid & 31;
    if (lane == 0) {
        s_red[warp][0] = sm;  s_red[warp][1] = sbm;
        s_red[warp][2] = sc;  s_red[warp][3] = sbc;
    }
    __syncthreads();
    if (tid == 0) {
        double a0 = 0, a1 = 0, a2 = 0, a3 = 0;
        #pragma unroll
        for (int w = 0; w < 8; w++) {
            a0 += (double)s_red[w][0];
            a1 += (double)s_red[w][1];
            a2 += (double)s_red[w][2];
            a3 += (double)s_red[w][3];
        }
        g_part[bx][0] = a0;
        g_part[bx][1] = a1;
        g_part[bx][2] = a2;
        g_part[bx][3] = a3;
    }
}

__global__ __launch_bounds__(THREADS)
void finalize_kernel(float* out) {
    __shared__ double s_acc[THREADS][4];
    const int tid = threadIdx.x;
    double a0 = 0, a1 = 0, a2 = 0, a3 = 0;
    for (int b = tid; b < TOTAL_BLOCKS; b += THREADS) {
        a0 += g_part[b][0];
        a1 += g_part[b][1];
        a2 += g_part[b][2];
        a3 += g_part[b][3];
    }
    s_acc[tid][0] = a0; s_acc[tid][1] = a1;
    s_acc[tid][2] = a2; s_acc[tid][3] = a3;
    __syncthreads();
    for (int s = THREADS / 2; s; s >>= 1) {
        if (tid < s) {
            s_acc[tid][0] += s_acc[tid + s][0];
            s_acc[tid][1] += s_acc[tid + s][1];
            s_acc[tid][2] += s_acc[tid + s][2];
            s_acc[tid][3] += s_acc[tid + s][3];
        }
        __syncthreads();
    }
    if (tid == 0) {
        double sum_mask = s_acc[0][0], sum_bm = s_acc[0][1];
        double s        = s_acc[0][2], sum_bc = s_acc[0][3];
        double loss;
        if (s > 0.0) loss = sum_bc / fmax(s, 1e-6);
        else         loss = sum_bm / fmax(sum_mask, 1e-6);
        out[0] = (float)loss;
    }
}

extern "C" void kernel_launch(void* const* d_in, const int* in_sizes, int n_in,
                              void* d_out, int out_size) {
    // Inputs (metadata order): pred_binary, gt, mask, image.
    // Defensive: locate image by its unique size (3*N*H*W); others keep order.
    const float* others[3];
    const float* img = nullptr;
    int k = 0;
    for (int i = 0; i < n_in; i++) {
        if (in_sizes[i] == NB * 3 * HW && img == nullptr) img = (const float*)d_in[i];
        else if (k < 3) others[k++] = (const float*)d_in[i];
    }
    const float* pred = others[0];
    const float* gt   = others[1];
    const float* mask = others[2];
    if (img == nullptr && n_in >= 4) img = (const float*)d_in[3];

    loss_kernel<<<TOTAL_BLOCKS, THREADS>>>(pred, gt, mask, img);
    finalize_kernel<<<1, THREADS>>>((float*)d_out);
}

// round 3
// speedup vs baseline: 1.0615x; 1.0615x over previous
#include <cuda_runtime.h>
#include <cstdint>

// Problem constants
#define NB 32
#define H 640
#define W 640
#define HW (H*W)            // 409600
#define BOT 448             // int(640*0.7)
#define RH 192              // region rows
#define TW 64               // strip width
#define HALO 5
#define TWH (TW + 2*HALO)   // 74
#define NSTRIP (W/TW)       // 10
#define STRIP_BLOCKS (NB*NSTRIP)   // 320
#define PLAIN_BLOCKS 864
#define TOTAL_BLOCKS (STRIP_BLOCKS + PLAIN_BLOCKS)  // 1184 = 148*8
#define THREADS 256
#define TOP_F4_PER_IMG ((BOT*W)/4) // 71680
#define TOP_F4_TOTAL (NB*TOP_F4_PER_IMG)            // 2293760
#define IMG_F4_STRIDE (HW/4)       // 102400
#define GSTRIDE (PLAIN_BLOCKS*THREADS)              // 221184 = 3*71680 + 6144
#define GSTRIDE_REM (GSTRIDE - 3*TOP_F4_PER_IMG)    // 6144

// Per-block partial sums + completion counter (zero-init; last block resets it
// each launch -> deterministic under graph replay).
__device__ double g_part[TOTAL_BLOCKS][4];
__device__ unsigned int g_done;   // static zero-init

__device__ __forceinline__ uint32_t bits_below(int k) {
    if (k <= 0) return 0u;
    if (k >= 32) return 0xFFFFFFFFu;
    return (1u << k) - 1u;
}

// Fast BCE-with-logits. Tolerance is 1e-3; __expf/__logf keep sum error ~1e-6.
__device__ __forceinline__ float bce_f(float l, float t) {
    return fmaxf(l, 0.f) - l * t + __logf(1.f + __expf(-fabsf(l)));
}

__device__ __forceinline__ void hsh(uint32_t w0, uint32_t w1, uint32_t w2,
                                    uint32_t& h0, uint32_t& h1, uint32_t& h2) {
    h0 = w0 | (w0 << 1) | (w0 >> 1) | (w1 << 31);
    h1 = w1 | (w1 << 1) | (w0 >> 31) | (w1 >> 1) | (w2 << 31);
    h2 = w2 | (w2 << 1) | (w1 >> 31) | (w2 >> 1);
}

// 3x3 morphology pass over bit-packed rows. erode == ~dilate(~m & valid) & valid,
// reproducing lax.reduce_window SAME semantics (OOB = identity element).
__device__ __forceinline__ void morph_pass(uint32_t (*in)[4], uint32_t (*out)[4],
                                           bool erode, const uint32_t* vm, int tid) {
    if (tid < RH) {
        int r = tid;
        uint32_t a0 = 0, a1 = 0, a2 = 0;
        #pragma unroll
        for (int dr = -1; dr <= 1; dr++) {
            int rr = r + dr;
            if ((unsigned)rr < (unsigned)RH) {
                uint32_t w0 = in[rr][0], w1 = in[rr][1], w2 = in[rr][2];
                if (erode) { w0 = ~w0 & vm[0]; w1 = ~w1 & vm[1]; w2 = ~w2 & vm[2]; }
                uint32_t h0, h1, h2;
                hsh(w0, w1, w2, h0, h1, h2);
                a0 |= h0; a1 |= h1; a2 |= h2;
            }
        }
        if (erode) { a0 = ~a0; a1 = ~a1; a2 = ~a2; }
        out[r][0] = a0 & vm[0];
        out[r][1] = a1 & vm[1];
        out[r][2] = a2 & vm[2];
        out[r][3] = 0u;
    }
    __syncthreads();
}

__global__ __launch_bounds__(THREADS)
void loss_kernel(const float* __restrict__ pred, const float* __restrict__ gt,
                 const float* __restrict__ mask, const float* __restrict__ img,
                 float* __restrict__ out)
{
    __shared__ uint8_t  s_gray[RH][80];     // gray tile, stride 80
    __shared__ uint32_t s_bA[RH][4];
    __shared__ uint32_t s_bB[RH][4];
    __shared__ float    s_red[8][4];
    __shared__ double   s_fin[64][4];
    __shared__ bool     s_last;

    const int tid = threadIdx.x;
    const int bx  = blockIdx.x;

    float sm = 0.f, sbm = 0.f, sc = 0.f, sbc = 0.f;

    if (bx < STRIP_BLOCKS) {
        // ---------------- subtitle-region strip block ----------------
        const int n = bx / NSTRIP;
        const int strip = bx - n * NSTRIP;
        const int c0 = strip * TW - HALO;             // may be negative
        const float* ib = img + (size_t)n * 3 * HW;

        // Load gray tile (u8). gray = rint(0.114*b + 0.587*g + 0.299*r) of floor-clipped u8.
        for (int idx = tid; idx < RH * TWH; idx += THREADS) {
            int r = idx / TWH;
            int t = idx - r * TWH;
            int gc = c0 + t;
            int g8 = 0;
            if ((unsigned)gc < (unsigned)W) {
                int base = (BOT + r) * W + gc;
                float b  = ib[base];
                float g  = ib[base + HW];
                float rr = ib[base + 2 * HW];
                b  = fminf(fmaxf(floorf(__fmul_rn(b , 255.f)), 0.f), 255.f);
                g  = fminf(fmaxf(floorf(__fmul_rn(g , 255.f)), 0.f), 255.f);
                rr = fminf(fmaxf(floorf(__fmul_rn(rr, 255.f)), 0.f), 255.f);
                float gf = __fadd_rn(__fadd_rn(__fmul_rn(0.114f, b),
                                               __fmul_rn(0.587f, g)),
                                     __fmul_rn(0.299f, rr));
                g8 = (int)rintf(gf);   // round-half-even, matches jnp.round
            }
            s_gray[r][t] = (uint8_t)g8;
        }
        __syncthreads();

        // Valid-column bitmask (tile cols mapping into [0, W))
        const int lo = (c0 < 0) ? -c0 : 0;
        const int hi = min(TWH, W - c0);
        uint32_t vm[4];
        #pragma unroll
        for (int j = 0; j < 4; j++)
            vm[j] = bits_below(hi - j * 32) & ~bits_below(lo - j * 32);

        // m0 = bright & contrast, bit-packed per row. Laplacian with reflect pad
        // at region borders; tile-edge cols away from the image border sit in the
        // 1-col validity shrink zone and are never consumed by the final mask.
        if (tid < RH) {
            int r = tid;
            uint32_t wq0 = 0, wq1 = 0, wq2 = 0;
            for (int t = 0; t < TWH; t++) {
                int gc = c0 + t;
                if ((unsigned)gc >= (unsigned)W) continue;
                int c = s_gray[r][t];
                if (c < 205) continue;   // bright: integer gray > 204.0000000116
                int up = (r == 0)      ? s_gray[1][t]      : s_gray[r - 1][t];
                int dn = (r == RH - 1) ? s_gray[RH - 2][t] : s_gray[r + 1][t];
                int lf, rt_;
                if (gc == 0)            lf = s_gray[r][t + 1];      // reflect
                else if (t == 0)        continue;                   // shrink zone
                else                    lf = s_gray[r][t - 1];
                if (gc == W - 1)        rt_ = s_gray[r][t - 1];     // reflect
                else if (t == TWH - 1)  continue;                   // shrink zone
                else                    rt_ = s_gray[r][t + 1];
                int lap = up + dn + lf + rt_ - 4 * c;
                if (lap >= 77 || lap <= -77) {                      // |lap| > 76.4999...
                    if (t < 32)       wq0 |= (1u << t);
                    else if (t < 64)  wq1 |= (1u << (t - 32));
                    else              wq2 |= (1u << (t - 64));
                }
            }
            s_bA[r][0] = wq0 & vm[0];
            s_bA[r][1] = wq1 & vm[1];
            s_bA[r][2] = wq2 & vm[2];
            s_bA[r][3] = 0u;
        }
        __syncthreads();

        // close (dilate, erode) then open (erode, dilate)
        morph_pass(s_bA, s_bB, false, vm, tid);  // m1 = dilate(m0)
        morph_pass(s_bB, s_bA, true,  vm, tid);  // m2 = erode(m1)
        morph_pass(s_bA, s_bB, true,  vm, tid);  // m3 = erode(m2)
        morph_pass(s_bB, s_bA, false, vm, tid);  // m4 = dilate(m3)  -> final in s_bA

        // Accumulate region sums (base + combined) over the 64-wide center.
        const int cbase = c0 + HALO;  // = strip*64, float4-aligned
        for (int idx = tid; idx < RH * (TW / 4); idx += THREADS) {  // 3072 total
            int r = idx >> 4;
            int q = idx & 15;
            size_t e = (size_t)n * HW + (size_t)(BOT + r) * W + cbase + q * 4;
            float4 mk = *(const float4*)(mask + e);
            float4 l  = *(const float4*)(pred + e);
            float4 tg = *(const float4*)(gt   + e);
            float b0 = bce_f(l.x, tg.x);
            float b1 = bce_f(l.y, tg.y);
            float b2 = bce_f(l.z, tg.z);
            float b3 = bce_f(l.w, tg.w);
            sm  += mk.x + mk.y + mk.z + mk.w;
            sbm += b0 * mk.x + b1 * mk.y + b2 * mk.z + b3 * mk.w;

            uint32_t w0 = s_bA[r][0], w1 = s_bA[r][1], w2 = s_bA[r][2];
            int t = HALO + q * 4;
            #pragma unroll
            for (int i = 0; i < 4; i++) {
                int tt = t + i;
                uint32_t bit = (tt < 32) ? (w0 >> tt)
                             : (tt < 64) ? (w1 >> (tt - 32))
                                         : (w2 >> (tt - 64));
                float f = (float)(bit & 1u);
                float mki = (i == 0) ? mk.x : (i == 1) ? mk.y : (i == 2) ? mk.z : mk.w;
                float bi  = (i == 0) ? b0   : (i == 1) ? b1   : (i == 2) ? b2   : b3;
                sc  += f * mki;
                sbc += f * bi * mki;
            }
        }
    } else {
        // ---------------- plain block: rows [0, 448) of each image ----------------
        const int lid = bx - STRIP_BLOCKS;
        const float4* p4 = (const float4*)pred;
        const float4* g4 = (const float4*)gt;
        const float4* m4 = (const float4*)mask;
        int i0 = lid * THREADS + tid;
        // decompose once; then advance with cheap carry (GSTRIDE = 3*TOP + 6144)
        int n   = i0 / TOP_F4_PER_IMG;
        int off = i0 - n * TOP_F4_PER_IMG;
        while (i0 < TOP_F4_TOTAL) {
            int e = n * IMG_F4_STRIDE + off;
            float4 mk = m4[e];
            float4 l  = p4[e];
            float4 tg = g4[e];
            sm  += mk.x + mk.y + mk.z + mk.w;
            sbm += bce_f(l.x, tg.x) * mk.x + bce_f(l.y, tg.y) * mk.y
                 + bce_f(l.z, tg.z) * mk.z + bce_f(l.w, tg.w) * mk.w;
            i0  += GSTRIDE;
            off += GSTRIDE_REM;
            n   += 3;
            if (off >= TOP_F4_PER_IMG) { off -= TOP_F4_PER_IMG; n++; }
        }
    }

    // ---------------- in-block reduction -> per-block slot ----------------
    #pragma unroll
    for (int o = 16; o; o >>= 1) {
        sm  += __shfl_down_sync(0xFFFFFFFFu, sm,  o);
        sbm += __shfl_down_sync(0xFFFFFFFFu, sbm, o);
        sc  += __shfl_down_sync(0xFFFFFFFFu, sc,  o);
        sbc += __shfl_down_sync(0xFFFFFFFFu, sbc, o);
    }
    int warp = tid >> 5, lane = tid & 31;
    if (lane == 0) {
        s_red[warp][0] = sm;  s_red[warp][1] = sbm;
        s_red[warp][2] = sc;  s_red[warp][3] = sbc;
    }
    __syncthreads();
    if (tid == 0) {
        double a0 = 0, a1 = 0, a2 = 0, a3 = 0;
        #pragma unroll
        for (int w = 0; w < 8; w++) {
            a0 += (double)s_red[w][0];
            a1 += (double)s_red[w][1];
            a2 += (double)s_red[w][2];
            a3 += (double)s_red[w][3];
        }
        g_part[bx][0] = a0;
        g_part[bx][1] = a1;
        g_part[bx][2] = a2;
        g_part[bx][3] = a3;
        __threadfence();
        unsigned prev = atomicAdd(&g_done, 1u);
        s_last = (prev == TOTAL_BLOCKS - 1);
    }
    __syncthreads();

    // ---------------- last block: final reduction + output ----------------
    if (s_last) {
        __threadfence();   // acquire all partials
        double a0 = 0, a1 = 0, a2 = 0, a3 = 0;
        for (int b = tid; b < TOTAL_BLOCKS; b += THREADS) {
            a0 += g_part[b][0];
            a1 += g_part[b][1];
            a2 += g_part[b][2];
            a3 += g_part[b][3];
        }
        int w2 = tid >> 5, l2 = tid & 31;
        #pragma unroll
        for (int o = 16; o; o >>= 1) {
            a0 += __shfl_down_sync(0xFFFFFFFFu, a0, o);
            a1 += __shfl_down_sync(0xFFFFFFFFu, a1, o);
            a2 += __shfl_down_sync(0xFFFFFFFFu, a2, o);
            a3 += __shfl_down_sync(0xFFFFFFFFu, a3, o);
        }
        if (l2 == 0) {
            s_fin[w2][0] = a0; s_fin[w2][1] = a1;
            s_fin[w2][2] = a2; s_fin[w2][3] = a3;
        }
        __syncthreads();
        if (tid == 0) {
            double b0 = 0, b1 = 0, b2 = 0, b3 = 0;
            #pragma unroll
            for (int w = 0; w < 8; w++) {
                b0 += s_fin[w][0]; b1 += s_fin[w][1];
                b2 += s_fin[w][2]; b3 += s_fin[w][3];
            }
            double loss;
            if (b2 > 0.0) loss = b3 / fmax(b2, 1e-6);
            else          loss = b1 / fmax(b0, 1e-6);
            out[0] = (float)loss;
            g_done = 0;        // reset for next graph replay
            __threadfence();
        }
    }
}

extern "C" void kernel_launch(void* const* d_in, const int* in_sizes, int n_in,
                              void* d_out, int out_size) {
    // Inputs (metadata order): pred_binary, gt, mask, image.
    // Defensive: locate image by its unique size (3*N*H*W); others keep order.
    const float* others[3];
    const float* img = nullptr;
    int k = 0;
    for (int i = 0; i < n_in; i++) {
        if (in_sizes[i] == NB * 3 * HW && img == nullptr) img = (const float*)d_in[i];
        else if (k < 3) others[k++] = (const float*)d_in[i];
    }
    const float* pred = others[0];
    const float* gt   = others[1];
    const float* mask = others[2];
    if (img == nullptr && n_in >= 4) img = (const float*)d_in[3];

    loss_kernel<<<TOTAL_BLOCKS, THREADS>>>(pred, gt, mask, img, (float*)d_out);
}

// round 4
// speedup vs baseline: 1.1474x; 1.0809x over previous
#include <cuda_runtime.h>
#include <cstdint>

// Problem constants
#define NB 32
#define H 640
#define W 640
#define HW (H*W)            // 409600
#define BOT 448             // int(640*0.7): region = rows [448, 640)
#define RH 192              // region rows
#define BANDS 6
#define BROWS 32            // owned rows per band
#define GHALO 5             // gray halo (m0 needs +-4, gray +-5)
#define TR (BROWS + 2*GHALO)   // 42 tile rows
#define WORDS 20            // 640 bits / 32
#define STRIP_BLOCKS (NB*BANDS)        // 192
#define PLAIN_F4_PER_BLOCK 2048
#define PLAIN_CHUNKS 35                // 35*2048 = 71680 = 448*640/4
#define PLAIN_BLOCKS (NB*PLAIN_CHUNKS) // 1120
#define TOTAL_BLOCKS (STRIP_BLOCKS + PLAIN_BLOCKS)  // 1312
#define THREADS 256
#define IMG_F4_STRIDE (HW/4)       // 102400

// Per-block partial sums + completion counter (zero-init; last block resets it
// each launch -> deterministic under graph replay).
__device__ double g_part[TOTAL_BLOCKS][4];
__device__ unsigned int g_done;   // static zero-init

// Fast BCE-with-logits. Tolerance is 1e-3; fast intrinsics keep sum error ~1e-6.
__device__ __forceinline__ float bce_f(float l, float t) {
    return fmaxf(l, 0.f) - l * t + __logf(1.f + __expf(-fabsf(l)));
}

__device__ __forceinline__ uint32_t vrow_of(int g) {
    return ((unsigned)g < (unsigned)RH) ? 0xFFFFFFFFu : 0u;
}

__device__ __forceinline__ uint32_t fetch_w(const uint32_t (*buf)[WORDS], int rr, int w,
                                            uint32_t v, bool erode) {
    if ((unsigned)w >= (unsigned)WORDS) return 0u;   // OOB column words -> 0 in both domains
    uint32_t x = buf[rr][w];
    return erode ? (~x & v) : x;
}

// One 3x3 morphology pass over bit-packed full-width rows (rows 1..40 computed).
// erode == ~dilate(~m & vrow) & vrow, reproducing lax.reduce_window SAME
// semantics (OOB = identity element) at region row borders and column edges.
__device__ __forceinline__ void morph_pass(const uint32_t (*in)[WORDS], uint32_t (*out)[WORDS],
                                           bool erode, int g0, int tid) {
    for (int idx = tid; idx < 40 * WORDS; idx += THREADS) {
        int r = 1 + idx / WORDS;
        int w = idx - (r - 1) * WORDS;
        uint32_t acc = 0;
        #pragma unroll
        for (int dr = -1; dr <= 1; dr++) {
            int rr = r + dr;                         // 0..41, always in tile
            uint32_t v  = vrow_of(g0 + rr);
            uint32_t x  = fetch_w(in, rr, w,     v, erode);
            uint32_t xl = fetch_w(in, rr, w - 1, v, erode);
            uint32_t xr = fetch_w(in, rr, w + 1, v, erode);
            acc |= x | (x << 1) | (x >> 1) | (xl >> 31) | (xr << 31);
        }
        if (erode) acc = ~acc;
        out[r][w] = acc & vrow_of(g0 + r);
    }
    __syncthreads();
}

__global__ __launch_bounds__(THREADS, 4)
void loss_kernel(const float* __restrict__ pred, const float* __restrict__ gt,
                 const float* __restrict__ mask, const float* __restrict__ img,
                 float* __restrict__ out)
{
    __shared__ uint32_t s_gray[TR][W/4];     // gray tile, u8 packed 4/word (26880 B)
    __shared__ uint32_t s_mA[TR][WORDS];
    __shared__ uint32_t s_mB[TR][WORDS];
    __shared__ float    s_red[8][4];
    __shared__ double   s_fin[8][4];
    __shared__ bool     s_last;

    const int tid = threadIdx.x;
    const int bx  = blockIdx.x;

    float sm = 0.f, sbm = 0.f, sc = 0.f, sbc = 0.f;

    if (bx < STRIP_BLOCKS) {
        // ---------------- subtitle-region band block ----------------
        const int n    = bx / BANDS;
        const int band = bx - n * BANDS;
        const int g0   = band * BROWS - GHALO;        // global region row of tile row 0
        const float* ib = img + (size_t)n * 3 * HW;

        // Load gray tile via float4 (fully coalesced). 42 rows x 160 f4 = 6720.
        // gray = rint(0.114*b + 0.587*g + 0.299*r) of floor(255x) clipped to [0,255].
        for (int idx = tid; idx < TR * (W/4); idx += THREADS) {   // ~27 iters
            int r  = idx / (W/4);
            int c4 = idx - r * (W/4);
            int g  = g0 + r;
            uint32_t packed = 0u;
            if ((unsigned)g < (unsigned)RH) {
                int base = (BOT + g) * (W/4) + c4;
                float4 bb = ((const float4*)ib)[base];
                float4 gg = ((const float4*)ib)[base + HW/4];
                float4 rr = ((const float4*)ib)[base + 2*(HW/4)];
                #pragma unroll
                for (int i = 0; i < 4; i++) {
                    float b = (i==0)?bb.x:(i==1)?bb.y:(i==2)?bb.z:bb.w;
                    float gch = (i==0)?gg.x:(i==1)?gg.y:(i==2)?gg.z:gg.w;
                    float rch = (i==0)?rr.x:(i==1)?rr.y:(i==2)?rr.z:rr.w;
                    b   = fminf(fmaxf(floorf(__fmul_rn(b  , 255.f)), 0.f), 255.f);
                    gch = fminf(fmaxf(floorf(__fmul_rn(gch, 255.f)), 0.f), 255.f);
                    rch = fminf(fmaxf(floorf(__fmul_rn(rch, 255.f)), 0.f), 255.f);
                    float gf = __fadd_rn(__fadd_rn(__fmul_rn(0.114f, b),
                                                   __fmul_rn(0.587f, gch)),
                                         __fmul_rn(0.299f, rch));
                    int g8 = (int)rintf(gf);   // round-half-even, matches jnp.round
                    packed |= ((uint32_t)g8 & 0xFFu) << (8 * i);
                }
            }
            s_gray[r][c4] = packed;
        }
        // Zero morph-buffer boundary rows (read but their results never consumed).
        if (tid < WORDS) {
            s_mA[0][tid] = 0u; s_mA[TR-1][tid] = 0u;
            s_mB[0][tid] = 0u; s_mB[TR-1][tid] = 0u;
        }
        __syncthreads();

        // m0 = bright & contrast, bit-packed, rows 1..40. Laplacian with reflect
        // padding at region row/col borders (rows: g==0 / g==RH-1; cols: 0 / 639).
        const uint8_t* G = (const uint8_t*)s_gray;
        for (int idx = tid; idx < 40 * WORDS; idx += THREADS) {
            int r = 1 + idx / WORDS;
            int w = idx - (r - 1) * WORDS;
            int g = g0 + r;
            uint32_t word = 0u;
            if ((unsigned)g < (unsigned)RH) {
                const uint8_t* row = G + r * W;
                const uint8_t* up_row = (g == 0)      ? G + (r + 1) * W : G + (r - 1) * W;
                const uint8_t* dn_row = (g == RH - 1) ? G + (r - 1) * W : G + (r + 1) * W;
                #pragma unroll 4
                for (int bit = 0; bit < 32; bit++) {
                    int c = w * 32 + bit;
                    int cc = row[c];
                    if (cc < 205) continue;   // bright: integer gray > 204.0000000116
                    int lf = (c == 0)     ? row[1]     : row[c - 1];
                    int rt = (c == W - 1) ? row[W - 2] : row[c + 1];
                    int lap = up_row[c] + dn_row[c] + lf + rt - 4 * cc;
                    if (lap >= 77 || lap <= -77)       // |lap| > 76.4999...
                        word |= (1u << bit);
                }
            }
            s_mA[r][w] = word;
        }
        __syncthreads();

        // close (dilate, erode) then open (erode, dilate)
        morph_pass(s_mA, s_mB, false, g0, tid);  // m1 = dilate(m0)
        morph_pass(s_mB, s_mA, true,  g0, tid);  // m2 = erode(m1)
        morph_pass(s_mA, s_mB, true,  g0, tid);  // m3 = erode(m2)
        morph_pass(s_mB, s_mA, false, g0, tid);  // m4 = dilate(m3) -> final in s_mA

        // Accumulate region sums over the band's 32 owned rows (tile rows 5..36).
        for (int idx = tid; idx < BROWS * (W/4); idx += THREADS) {  // 20 iters
            int r  = GHALO + idx / (W/4);
            int c4 = idx - (r - GHALO) * (W/4);
            int g  = g0 + r;                     // = band*BROWS + (r-GHALO)
            int e  = n * HW + (BOT + g) * W + c4 * 4;
            float4 mk = *(const float4*)(mask + e);
            float4 l  = *(const float4*)(pred + e);
            float4 tg = *(const float4*)(gt   + e);
            float b0 = bce_f(l.x, tg.x);
            float b1 = bce_f(l.y, tg.y);
            float b2 = bce_f(l.z, tg.z);
            float b3 = bce_f(l.w, tg.w);
            sm  += mk.x + mk.y + mk.z + mk.w;
            sbm += b0 * mk.x + b1 * mk.y + b2 * mk.z + b3 * mk.w;

            uint32_t mword = s_mA[r][c4 >> 3];
            int sh = (c4 & 7) * 4;
            float f0 = (float)((mword >> (sh + 0)) & 1u);
            float f1 = (float)((mword >> (sh + 1)) & 1u);
            float f2 = (float)((mword >> (sh + 2)) & 1u);
            float f3 = (float)((mword >> (sh + 3)) & 1u);
            sc  += f0 * mk.x + f1 * mk.y + f2 * mk.z + f3 * mk.w;
            sbc += f0 * b0 * mk.x + f1 * b1 * mk.y + f2 * b2 * mk.z + f3 * b3 * mk.w;
        }
    } else {
        // ---------------- plain block: rows [0, 448) of one image ----------------
        const int p     = bx - STRIP_BLOCKS;
        const int nimg  = p / PLAIN_CHUNKS;
        const int chunk = p - nimg * PLAIN_CHUNKS;
        const int base  = nimg * IMG_F4_STRIDE + chunk * PLAIN_F4_PER_BLOCK;
        const float4* p4 = (const float4*)pred;
        const float4* g4 = (const float4*)gt;
        const float4* m4 = (const float4*)mask;
        #pragma unroll
        for (int u = 0; u < PLAIN_F4_PER_BLOCK / THREADS; u++) {   // 8, static
            int e = base + u * THREADS + tid;
            float4 mk = m4[e];
            float4 l  = p4[e];
            float4 tg = g4[e];
            sm  += mk.x + mk.y + mk.z + mk.w;
            sbm += bce_f(l.x, tg.x) * mk.x + bce_f(l.y, tg.y) * mk.y
                 + bce_f(l.z, tg.z) * mk.z + bce_f(l.w, tg.w) * mk.w;
        }
    }

    // ---------------- in-block reduction -> per-block slot ----------------
    #pragma unroll
    for (int o = 16; o; o >>= 1) {
        sm  += __shfl_down_sync(0xFFFFFFFFu, sm,  o);
        sbm += __shfl_down_sync(0xFFFFFFFFu, sbm, o);
        sc  += __shfl_down_sync(0xFFFFFFFFu, sc,  o);
        sbc += __shfl_down_sync(0xFFFFFFFFu, sbc, o);
    }
    int warp = tid >> 5, lane = tid & 31;
    if (lane == 0) {
        s_red[warp][0] = sm;  s_red[warp][1] = sbm;
        s_red[warp][2] = sc;  s_red[warp][3] = sbc;
    }
    __syncthreads();
    if (tid == 0) {
        double a0 = 0, a1 = 0, a2 = 0, a3 = 0;
        #pragma unroll
        for (int w = 0; w < 8; w++) {
            a0 += (double)s_red[w][0];
            a1 += (double)s_red[w][1];
            a2 += (double)s_red[w][2];
            a3 += (double)s_red[w][3];
        }
        g_part[bx][0] = a0;
        g_part[bx][1] = a1;
        g_part[bx][2] = a2;
        g_part[bx][3] = a3;
        __threadfence();
        unsigned prev = atomicAdd(&g_done, 1u);
        s_last = (prev == TOTAL_BLOCKS - 1);
    }
    __syncthreads();

    // ---------------- last block: final reduction + output ----------------
    if (s_last) {
        __threadfence();   // acquire all partials
        double a0 = 0, a1 = 0, a2 = 0, a3 = 0;
        for (int b = tid; b < TOTAL_BLOCKS; b += THREADS) {
            a0 += g_part[b][0];
            a1 += g_part[b][1];
            a2 += g_part[b][2];
            a3 += g_part[b][3];
        }
        int w2 = tid >> 5, l2 = tid & 31;
        #pragma unroll
        for (int o = 16; o; o >>= 1) {
            a0 += __shfl_down_sync(0xFFFFFFFFu, a0, o);
            a1 += __shfl_down_sync(0xFFFFFFFFu, a1, o);
            a2 += __shfl_down_sync(0xFFFFFFFFu, a2, o);
            a3 += __shfl_down_sync(0xFFFFFFFFu, a3, o);
        }
        if (l2 == 0) {
            s_fin[w2][0] = a0; s_fin[w2][1] = a1;
            s_fin[w2][2] = a2; s_fin[w2][3] = a3;
        }
        __syncthreads();
        if (tid == 0) {
            double b0 = 0, b1 = 0, b2 = 0, b3 = 0;
            #pragma unroll
            for (int w = 0; w < 8; w++) {
                b0 += s_fin[w][0]; b1 += s_fin[w][1];
                b2 += s_fin[w][2]; b3 += s_fin[w][3];
            }
            double loss;
            if (b2 > 0.0) loss = b3 / fmax(b2, 1e-6);
            else          loss = b1 / fmax(b0, 1e-6);
            out[0] = (float)loss;
            g_done = 0;        // reset for next graph replay
            __threadfence();
        }
    }
}

extern "C" void kernel_launch(void* const* d_in, const int* in_sizes, int n_in,
                              void* d_out, int out_size) {
    // Inputs (metadata order): pred_binary, gt, mask, image.
    // Defensive: locate image by its unique size (3*N*H*W); others keep order.
    const float* others[3];
    const float* img = nullptr;
    int k = 0;
    for (int i = 0; i < n_in; i++) {
        if (in_sizes[i] == NB * 3 * HW && img == nullptr) img = (const float*)d_in[i];
        else if (k < 3) others[k++] = (const float*)d_in[i];
    }
    const float* pred = others[0];
    const float* gt   = others[1];
    const float* mask = others[2];
    if (img == nullptr && n_in >= 4) img = (const float*)d_in[3];

    loss_kernel<<<TOTAL_BLOCKS, THREADS>>>(pred, gt, mask, img, (float*)d_out);
}

// round 5
// speedup vs baseline: 1.6135x; 1.4061x over previous
#include <cuda_runtime.h>
#include <cstdint>

// Problem constants
#define NB 32
#define H 640
#define W 640
#define HW (H*W)            // 409600
#define BOT 448             // int(640*0.7): region = rows [448, 640)
#define RH 192              // region rows
#define BROWS 32            // owned rows per band (6 bands)
#define GHALO 5
#define TR (BROWS + 2*GHALO)   // 42 tile rows
#define GW4 84              // gray tile width in u32 (336 bytes: cols gbase..gbase+335)
#define MW 12               // mask words per row (384 bits window)
#define THREADS 256
#define TOTAL_BLOCKS 592    // 148 SMs * 4 resident blocks = one full wave
#define STRIPS 384          // 32 img * 6 bands * 2 halves
#define CHUNK_F4 1024
#define CHUNKS_PER_IMG 70   // 71680/1024
#define N_CHUNKS (NB*CHUNKS_PER_IMG)   // 2240
#define IMG_F4_STRIDE (HW/4)

__device__ double g_part[TOTAL_BLOCKS][4];
__device__ unsigned int g_done;   // static zero-init; reset by last block each launch

__device__ __forceinline__ float bce_f(float l, float t) {
    return fmaxf(l, 0.f) - l * t + __logf(1.f + __expf(-fabsf(l)));
}

__device__ __forceinline__ uint32_t vrow_of(int g) {
    return ((unsigned)g < (unsigned)RH) ? 0xFFFFFFFFu : 0u;
}

__device__ __forceinline__ uint32_t fetch_w(const uint32_t (*buf)[MW], int rr, int w,
                                            uint32_t v, bool erode) {
    if ((unsigned)w >= (unsigned)MW) return 0u;
    uint32_t x = buf[rr][w];
    return erode ? (~x & v) : x;
}

// 3x3 morphology pass, bit-packed. erode == ~dilate(~m & valid) & valid
// (reduce_window SAME identity semantics at region borders / image cols).
__device__ __forceinline__ void morph_pass(const uint32_t (*in)[MW], uint32_t (*out)[MW],
                                           bool erode, int g0, uint32_t vm0, uint32_t vm11,
                                           int tid) {
    for (int idx = tid; idx < 40 * MW; idx += THREADS) {   // 2 iters
        int r = 1 + idx / MW;
        int w = idx - (r - 1) * MW;
        uint32_t vcol = (w == 0) ? vm0 : (w == MW - 1) ? vm11 : 0xFFFFFFFFu;
        uint32_t acc = 0;
        #pragma unroll
        for (int dr = -1; dr <= 1; dr++) {
            int rr = r + dr;                       // always within tile rows 0..41
            uint32_t v  = vrow_of(g0 + rr) & vcol;
            uint32_t vl = vrow_of(g0 + rr) & ((w - 1 == 0) ? vm0 : 0xFFFFFFFFu);
            uint32_t vr = vrow_of(g0 + rr) & ((w + 1 == MW - 1) ? vm11 : 0xFFFFFFFFu);
            uint32_t x  = fetch_w(in, rr, w,     v,  erode);
            uint32_t xl = fetch_w(in, rr, w - 1, vl, erode);
            uint32_t xr = fetch_w(in, rr, w + 1, vr, erode);
            acc |= x | (x << 1) | (x >> 1) | (xl >> 31) | (xr << 31);
        }
        if (erode) acc = ~acc;
        out[r][w] = acc & vrow_of(g0 + r) & vcol;
    }
    __syncthreads();
}

__device__ __forceinline__ void plain_chunk(int c, int tid,
                                            const float4* p4, const float4* g4,
                                            const float4* m4,
                                            float& sm, float& sbm) {
    int n    = c / CHUNKS_PER_IMG;
    int coff = (c - n * CHUNKS_PER_IMG) * CHUNK_F4;
    int base = n * IMG_F4_STRIDE + coff;
    #pragma unroll
    for (int u = 0; u < CHUNK_F4 / THREADS; u++) {    // 4
        int e = base + u * THREADS + tid;
        float4 mk = m4[e];
        float4 l  = p4[e];
        float4 tg = g4[e];
        sm  += mk.x + mk.y + mk.z + mk.w;
        sbm += bce_f(l.x, tg.x) * mk.x + bce_f(l.y, tg.y) * mk.y
             + bce_f(l.z, tg.z) * mk.z + bce_f(l.w, tg.w) * mk.w;
    }
}

__global__ __launch_bounds__(THREADS, 4)
void loss_kernel(const float* __restrict__ pred, const float* __restrict__ gt,
                 const float* __restrict__ mask, const float* __restrict__ img,
                 float* __restrict__ out)
{
    __shared__ uint32_t s_gray[TR][GW4];     // 14112 B
    __shared__ uint32_t s_mA[TR][MW];        // 2016 B
    __shared__ uint32_t s_mB[TR][MW];        // 2016 B
    __shared__ float    s_red[8][4];
    __shared__ double   s_fin[8][4];
    __shared__ bool     s_last;

    const int tid = threadIdx.x;
    const int bx  = blockIdx.x;
    const float4* p4 = (const float4*)pred;
    const float4* g4 = (const float4*)gt;
    const float4* m4 = (const float4*)mask;

    float sm = 0.f, sbm = 0.f, sc = 0.f, sbc = 0.f;

    const bool is_strip = (bx < 576) && ((bx % 3) < 2);

    if (is_strip) {
        // ---------------- subtitle half-band block ----------------
        const int hs    = 2 * (bx / 3) + (bx % 3);    // 0..383
        const int bandg = hs >> 1;
        const int h     = hs & 1;                     // column half
        const int n     = bandg / 6;
        const int band  = bandg - n * 6;
        const int g0    = band * BROWS - GHALO;       // region row of tile row 0
        const int gb4   = h * 80 - 2;                 // gray base col / 4 (gbase = h*320-8)
        const float* ib = img + (size_t)n * 3 * HW;

        // Gray tile load (coalesced float4): 42 x 84 = 3528 items.
        for (int idx = tid; idx < TR * GW4; idx += THREADS) {
            int r  = idx / GW4;
            int t4 = idx - r * GW4;
            int g  = g0 + r;
            int c4 = gb4 + t4;
            uint32_t packed = 0u;
            if ((unsigned)g < (unsigned)RH && (unsigned)c4 < (unsigned)(W/4)) {
                int base = (BOT + g) * (W/4) + c4;
                float4 bb = ((const float4*)ib)[base];
                float4 gg = ((const float4*)ib)[base + HW/4];
                float4 rr = ((const float4*)ib)[base + 2*(HW/4)];
                #pragma unroll
                for (int i = 0; i < 4; i++) {
                    float b   = (i==0)?bb.x:(i==1)?bb.y:(i==2)?bb.z:bb.w;
                    float gch = (i==0)?gg.x:(i==1)?gg.y:(i==2)?gg.z:gg.w;
                    float rch = (i==0)?rr.x:(i==1)?rr.y:(i==2)?rr.z:rr.w;
                    b   = fminf(fmaxf(floorf(__fmul_rn(b  , 255.f)), 0.f), 255.f);
                    gch = fminf(fmaxf(floorf(__fmul_rn(gch, 255.f)), 0.f), 255.f);
                    rch = fminf(fmaxf(floorf(__fmul_rn(rch, 255.f)), 0.f), 255.f);
                    float gf = __fadd_rn(__fadd_rn(__fmul_rn(0.114f, b),
                                                   __fmul_rn(0.587f, gch)),
                                         __fmul_rn(0.299f, rch));
                    int g8 = (int)rintf(gf);   // round-half-even = jnp.round
                    packed |= ((uint32_t)g8 & 0xFFu) << (8 * i);
                }
            }
            s_gray[r][t4] = packed;
        }
        if (tid < MW) {                 // boundary rows for morph buffers
            s_mA[0][tid] = 0u; s_mA[TR-1][tid] = 0u;
            s_mB[0][tid] = 0u; s_mB[TR-1][tid] = 0u;
        }
        __syncthreads();

        // m0 = bright & contrast, words m=0..11 (global cols h*320-32+32m+bit).
        const uint8_t* G = (const uint8_t*)s_gray;
        for (int idx = tid; idx < 40 * MW; idx += THREADS) {   // 2 iters
            int r = 1 + idx / MW;
            int m = idx - (r - 1) * MW;
            int g = g0 + r;
            uint32_t word = 0u;
            if ((unsigned)g < (unsigned)RH) {
                // bright mask via SIMD byte compare over the 8 gray u32s
                uint32_t bright = 0u;
                #pragma unroll
                for (int j = 0; j < 8; j++) {
                    int t4 = 8 * m - 6 + j;
                    if ((unsigned)t4 < (unsigned)GW4) {
                        uint32_t one = __vsetgeu4(s_gray[r][t4], 0xCDCDCDCDu); // >=205
                        bright |= (((one & 0x01010101u) * 0x01020408u) >> 24 & 0xFu) << (4 * j);
                    }
                }
                int ru = (g == 0)      ? r + 1 : r - 1;
                int rd = (g == RH - 1) ? r - 1 : r + 1;
                const uint8_t* row = G + r * (GW4 * 4);
                const uint8_t* upr = G + ru * (GW4 * 4);
                const uint8_t* dnr = G + rd * (GW4 * 4);
                while (bright) {
                    int bit = __ffs(bright) - 1; bright &= bright - 1;
                    int t  = 32 * m + bit - 24;
                    int gc = h * 320 + 32 * m + bit - 32;
                    if ((unsigned)gc >= (unsigned)W) continue;
                    int tl = (gc == 0)     ? t + 1 : t - 1;
                    int tr_ = (gc == W - 1) ? t - 1 : t + 1;
                    if ((unsigned)tl >= 336u || (unsigned)tr_ >= 336u) continue; // halo margin
                    int cc = row[t];
                    int lap = upr[t] + dnr[t] + row[tl] + row[tr_] - 4 * cc;
                    if (lap >= 77 || lap <= -77)
                        word |= (1u << bit);
                }
            }
            s_mA[r][m] = word;
        }
        __syncthreads();

        // vm for edge words: h=0 word0 = cols<0; h=1 word11 = cols>=640.
        const uint32_t vm0  = (h == 0) ? 0u : 0xFFFFFFFFu;
        const uint32_t vm11 = (h == 1) ? 0u : 0xFFFFFFFFu;

        morph_pass(s_mA, s_mB, false, g0, vm0, vm11, tid);  // dilate
        morph_pass(s_mB, s_mA, true,  g0, vm0, vm11, tid);  // erode  (close done)
        morph_pass(s_mA, s_mB, true,  g0, vm0, vm11, tid);  // erode
        morph_pass(s_mB, s_mA, false, g0, vm0, vm11, tid);  // dilate (open done)

        // Region sums over owned 32 rows x 320 cols.
        for (int idx = tid; idx < BROWS * 80; idx += THREADS) {   // 10 iters
            int r   = GHALO + idx / 80;
            int c4l = idx - (r - GHALO) * 80;
            int g   = g0 + r;
            int e   = n * HW + (BOT + g) * W + h * 320 + c4l * 4;
            float4 mk = *(const float4*)(mask + e);
            float4 l  = *(const float4*)(pred + e);
            float4 tg = *(const float4*)(gt   + e);
            float b0 = bce_f(l.x, tg.x);
            float b1 = bce_f(l.y, tg.y);
            float b2 = bce_f(l.z, tg.z);
            float b3 = bce_f(l.w, tg.w);
            sm  += mk.x + mk.y + mk.z + mk.w;
            sbm += b0 * mk.x + b1 * mk.y + b2 * mk.z + b3 * mk.w;

            uint32_t mword = s_mA[r][1 + (c4l >> 3)];   // owned word = 1 + col/32
            int sh = (c4l & 7) * 4;
            float f0 = (float)((mword >> (sh + 0)) & 1u);
            float f1 = (float)((mword >> (sh + 1)) & 1u);
            float f2 = (float)((mword >> (sh + 2)) & 1u);
            float f3 = (float)((mword >> (sh + 3)) & 1u);
            sc  += f0 * mk.x + f1 * mk.y + f2 * mk.z + f3 * mk.w;
            sbc += f0 * b0 * mk.x + f1 * b1 * mk.y + f2 * b2 * mk.z + f3 * b3 * mk.w;
        }

        // Plain tail: 2 chunks per strip block (chunks 0..767).
        plain_chunk(hs * 2 + 0, tid, p4, g4, m4, sm, sbm);
        plain_chunk(hs * 2 + 1, tid, p4, g4, m4, sm, sbm);
    } else {
        // ---------------- plain block ----------------
        int j;   // plain rank 0..207
        if ((bx % 3) == 2) j = bx / 3;
        else               j = 197 + (2 * (bx / 3) + (bx % 3) - STRIPS);
        int start = 768 + ((j < 16) ? j * 8 : 128 + (j - 16) * 7);
        int cnt   = (j < 16) ? 8 : 7;
        for (int q = 0; q < cnt; q++)
            plain_chunk(start + q, tid, p4, g4, m4, sm, sbm);
    }

    // ---------------- in-block reduction -> per-block slot ----------------
    #pragma unroll
    for (int o = 16; o; o >>= 1) {
        sm  += __shfl_down_sync(0xFFFFFFFFu, sm,  o);
        sbm += __shfl_down_sync(0xFFFFFFFFu, sbm, o);
        sc  += __shfl_down_sync(0xFFFFFFFFu, sc,  o);
        sbc += __shfl_down_sync(0xFFFFFFFFu, sbc, o);
    }
    int warp = tid >> 5, lane = tid & 31;
    if (lane == 0) {
        s_red[warp][0] = sm;  s_red[warp][1] = sbm;
        s_red[warp][2] = sc;  s_red[warp][3] = sbc;
    }
    __syncthreads();
    if (tid == 0) {
        double a0 = 0, a1 = 0, a2 = 0, a3 = 0;
        #pragma unroll
        for (int w = 0; w < 8; w++) {
            a0 += (double)s_red[w][0];
            a1 += (double)s_red[w][1];
            a2 += (double)s_red[w][2];
            a3 += (double)s_red[w][3];
        }
        g_part[bx][0] = a0;
        g_part[bx][1] = a1;
        g_part[bx][2] = a2;
        g_part[bx][3] = a3;
        __threadfence();
        unsigned prev = atomicAdd(&g_done, 1u);
        s_last = (prev == TOTAL_BLOCKS - 1);
    }
    __syncthreads();

    if (s_last) {
        __threadfence();
        double a0 = 0, a1 = 0, a2 = 0, a3 = 0;
        for (int b = tid; b < TOTAL_BLOCKS; b += THREADS) {
            a0 += g_part[b][0];
            a1 += g_part[b][1];
            a2 += g_part[b][2];
            a3 += g_part[b][3];
        }
        int w2 = tid >> 5, l2 = tid & 31;
        #pragma unroll
        for (int o = 16; o; o >>= 1) {
            a0 += __shfl_down_sync(0xFFFFFFFFu, a0, o);
            a1 += __shfl_down_sync(0xFFFFFFFFu, a1, o);
            a2 += __shfl_down_sync(0xFFFFFFFFu, a2, o);
            a3 += __shfl_down_sync(0xFFFFFFFFu, a3, o);
        }
        if (l2 == 0) {
            s_fin[w2][0] = a0; s_fin[w2][1] = a1;
            s_fin[w2][2] = a2; s_fin[w2][3] = a3;
        }
        __syncthreads();
        if (tid == 0) {
            double b0 = 0, b1 = 0, b2 = 0, b3 = 0;
            #pragma unroll
            for (int w = 0; w < 8; w++) {
                b0 += s_fin[w][0]; b1 += s_fin[w][1];
                b2 += s_fin[w][2]; b3 += s_fin[w][3];
            }
            double loss;
            if (b2 > 0.0) loss = b3 / fmax(b2, 1e-6);
            else          loss = b1 / fmax(b0, 1e-6);
            out[0] = (float)loss;
            g_done = 0;
            __threadfence();
        }
    }
}

extern "C" void kernel_launch(void* const* d_in, const int* in_sizes, int n_in,
                              void* d_out, int out_size) {
    const float* others[3];
    const float* img = nullptr;
    int k = 0;
    for (int i = 0; i < n_in; i++) {
        if (in_sizes[i] == NB * 3 * HW && img == nullptr) img = (const float*)d_in[i];
        else if (k < 3) others[k++] = (const float*)d_in[i];
    }
    const float* pred = others[0];
    const float* gt   = others[1];
    const float* mask = others[2];
    if (img == nullptr && n_in >= 4) img = (const float*)d_in[3];

    loss_kernel<<<TOTAL_BLOCKS, THREADS>>>(pred, gt, mask, img, (float*)d_out);
}